// round 5
// baseline (speedup 1.0000x reference)
#include <cuda_runtime.h>
#include <math.h>
#include <stdint.h>

#define SDIM 64
#define HDIM 128
#define KC   512
#define ADIM 8
#define TM   128
#define NT   512

// ---- shared arena (float offsets) ----
// MLP era:     s_in[128][68] @0 | s_w[128][128] @8704 | s_h[128][132] @25088
// tensor era:  x_hi[128][132] @0 | x_lo @16896 | e_hi[64][136] @33792 |
//              e_lo @42496 | enorm[512] @51200
#define S_IN      0
#define SI_STRIDE 68
#define S_W       8704
#define S_H       25088
#define SH_STRIDE 132
#define X_HI      0
#define X_LO      16896
#define XSTRIDE   132
#define E_HI      33792
#define E_LO      42496
#define ESTRIDE   136
#define ENORM     51200
#define ARENA_FLOATS 51712    // 206,848 bytes

__device__ float g_probs[KC * ADIM];
__device__ float g_value[KC];
__device__ float g_enorm[KC];
__device__ float g_ehi[KC * HDIM];
__device__ float g_elo[KC * HDIM];

// ---------------- helpers ----------------
__device__ __forceinline__ float2 ffma2(float2 a, float2 b, float2 c) {
    float2 d;
    asm("fma.rn.f32x2 %0, %1, %2, %3;"
        : "=l"(reinterpret_cast<unsigned long long&>(d))
        : "l"(reinterpret_cast<unsigned long long&>(a)),
          "l"(reinterpret_cast<unsigned long long&>(b)),
          "l"(reinterpret_cast<unsigned long long&>(c)));
    return d;
}
__device__ __forceinline__ float tf32_rna(float v) {
    uint32_t u;
    asm("cvt.rna.tf32.f32 %0, %1;" : "=r"(u) : "f"(v));
    return __uint_as_float(u);
}
// D += A(16x8,row) * B(8x8,col) ; tf32 inputs in b32 regs, fp32 accum
__device__ __forceinline__ void mma_tf32(float c[4], const float a[4], const float b[2]) {
    asm volatile(
        "mma.sync.aligned.m16n8k8.row.col.f32.tf32.tf32.f32 "
        "{%0,%1,%2,%3}, {%4,%5,%6,%7}, {%8,%9}, {%0,%1,%2,%3};"
        : "+f"(c[0]), "+f"(c[1]), "+f"(c[2]), "+f"(c[3])
        : "r"(__float_as_uint(a[0])), "r"(__float_as_uint(a[1])),
          "r"(__float_as_uint(a[2])), "r"(__float_as_uint(a[3])),
          "r"(__float_as_uint(b[0])), "r"(__float_as_uint(b[1])));
}
__device__ __forceinline__ unsigned long long packkey(float d, int code) {
    uint32_t u = __float_as_uint(d);
    u = (u & 0x80000000u) ? ~u : (u | 0x80000000u);   // order-preserving map
    return ((unsigned long long)u << 32) | (uint32_t)code;
}

// ---------------------------------------------------------------------------
// Kernel 0: per-code head precompute + tf32 hi/lo codebook split.
// ---------------------------------------------------------------------------
__global__ void head_kernel(const float* __restrict__ E,
                            const float* __restrict__ Wa,
                            const float* __restrict__ ba,
                            const float* __restrict__ Wv,
                            const float* __restrict__ bv) {
    int c = blockIdx.x * blockDim.x + threadIdx.x;
    if (c >= KC) return;
    float logit[ADIM];
#pragma unroll
    for (int a = 0; a < ADIM; a++) logit[a] = ba[a];
    float en = 0.f, val = bv[0];
    for (int k = 0; k < HDIM; k++) {
        float ev = E[c * HDIM + k];
        en  = fmaf(ev, ev, en);
        val = fmaf(ev, Wv[k], val);
        float hi = tf32_rna(ev);
        g_ehi[c * HDIM + k] = hi;
        g_elo[c * HDIM + k] = tf32_rna(ev - hi);
#pragma unroll
        for (int a = 0; a < ADIM; a++)
            logit[a] = fmaf(ev, Wa[k * ADIM + a], logit[a]);
    }
    float m = logit[0];
#pragma unroll
    for (int a = 1; a < ADIM; a++) m = fmaxf(m, logit[a]);
    float s = 0.f;
#pragma unroll
    for (int a = 0; a < ADIM; a++) { logit[a] = expf(logit[a] - m); s += logit[a]; }
    float inv = 1.f / s;
#pragma unroll
    for (int a = 0; a < ADIM; a++) g_probs[c * ADIM + a] = logit[a] * inv;
    g_value[c] = val;
    g_enorm[c] = en;
}

// ---------------------------------------------------------------------------
// Fused kernel: FFMA2 scalar MLP -> tf32x3 mma.sync distance GEMM -> argmin.
// ---------------------------------------------------------------------------
__global__ __launch_bounds__(NT, 1)
void fused_kernel(const float* __restrict__ in,
                  const float* __restrict__ W1,
                  const float* __restrict__ b1,
                  const float* __restrict__ Wh,
                  const float* __restrict__ bh,
                  float* __restrict__ out,
                  int nrows) {
    extern __shared__ float sm[];
    __shared__ unsigned long long s_best[TM];

    const int tid  = threadIdx.x;
    const int wid  = tid >> 5, lane = tid & 31;
    const int rbase = wid * 8;
    const int row0 = blockIdx.x * TM;

    float* s_in = sm + S_IN;
    float* s_w  = sm + S_W;
    float* s_h  = sm + S_H;

    // ---- load input tile + W1 ----
    for (int i = tid; i < TM * SDIM; i += NT) {
        int r = i >> 6, k = i & 63;
        s_in[r * SI_STRIDE + k] = in[(size_t)(row0 + r) * SDIM + k];
    }
    for (int i = tid; i < SDIM * HDIM; i += NT) s_w[i] = W1[i];
    __syncthreads();

    float2 acc[8][2];

    // ---- Phase 1: h = relu(in @ W1 + b1) ----
    {
        float4 bb = *(const float4*)&b1[4 * lane];
#pragma unroll
        for (int i = 0; i < 8; i++) {
            acc[i][0] = make_float2(bb.x, bb.y);
            acc[i][1] = make_float2(bb.z, bb.w);
        }
#pragma unroll 1
        for (int k4 = 0; k4 < SDIM; k4 += 4) {
            float a4[8][4];
#pragma unroll
            for (int i = 0; i < 8; i++)
                *(float4*)&a4[i][0] = *(const float4*)&s_in[(rbase + i) * SI_STRIDE + k4];
#pragma unroll
            for (int j = 0; j < 4; j++) {
                float4 b4 = *(const float4*)&s_w[(k4 + j) * HDIM + 4 * lane];
                float2 blo = make_float2(b4.x, b4.y), bhi = make_float2(b4.z, b4.w);
#pragma unroll
                for (int i = 0; i < 8; i++) {
                    float2 a2 = make_float2(a4[i][j], a4[i][j]);
                    acc[i][0] = ffma2(a2, blo, acc[i][0]);
                    acc[i][1] = ffma2(a2, bhi, acc[i][1]);
                }
            }
        }
    }
#pragma unroll
    for (int i = 0; i < 8; i++) {
        float4 v = make_float4(fmaxf(acc[i][0].x, 0.f), fmaxf(acc[i][0].y, 0.f),
                               fmaxf(acc[i][1].x, 0.f), fmaxf(acc[i][1].y, 0.f));
        *(float4*)&s_h[(rbase + i) * SH_STRIDE + 4 * lane] = v;
    }
    __syncthreads();
    for (int i = tid; i < HDIM * HDIM; i += NT) s_w[i] = Wh[i];
    __syncthreads();

    // ---- Phase 2: x = relu(h @ Wh + bh) ----
    {
        float4 bb = *(const float4*)&bh[4 * lane];
#pragma unroll
        for (int i = 0; i < 8; i++) {
            acc[i][0] = make_float2(bb.x, bb.y);
            acc[i][1] = make_float2(bb.z, bb.w);
        }
#pragma unroll 1
        for (int k4 = 0; k4 < HDIM; k4 += 4) {
            float a4[8][4];
#pragma unroll
            for (int i = 0; i < 8; i++)
                *(float4*)&a4[i][0] = *(const float4*)&s_h[(rbase + i) * SH_STRIDE + k4];
#pragma unroll
            for (int j = 0; j < 4; j++) {
                float4 b4 = *(const float4*)&s_w[(k4 + j) * HDIM + 4 * lane];
                float2 blo = make_float2(b4.x, b4.y), bhi = make_float2(b4.z, b4.w);
#pragma unroll
                for (int i = 0; i < 8; i++) {
                    float2 a2 = make_float2(a4[i][j], a4[i][j]);
                    acc[i][0] = ffma2(a2, blo, acc[i][0]);
                    acc[i][1] = ffma2(a2, bhi, acc[i][1]);
                }
            }
        }
    }
    __syncthreads();   // all MLP smem reads complete; arena re-purposed

    // ---- split x into tf32 hi/lo tiles ----
    {
        float* xh = sm + X_HI;
        float* xl = sm + X_LO;
        const int c = 4 * lane;
#pragma unroll
        for (int i = 0; i < 8; i++) {
            int r = rbase + i;
            float x0 = fmaxf(acc[i][0].x, 0.f), x1 = fmaxf(acc[i][0].y, 0.f);
            float x2 = fmaxf(acc[i][1].x, 0.f), x3 = fmaxf(acc[i][1].y, 0.f);
            float h0 = tf32_rna(x0), h1 = tf32_rna(x1), h2 = tf32_rna(x2), h3 = tf32_rna(x3);
            *(float4*)&xh[r * XSTRIDE + c] = make_float4(h0, h1, h2, h3);
            *(float4*)&xl[r * XSTRIDE + c] =
                make_float4(tf32_rna(x0 - h0), tf32_rna(x1 - h1),
                            tf32_rna(x2 - h2), tf32_rna(x3 - h3));
        }
    }
    for (int i = tid; i < KC; i += NT) sm[ENORM + i] = g_enorm[i];
    for (int i = tid; i < TM; i += NT) s_best[i] = ~0ULL;

    // ---- distance GEMM via tf32x3 mma.sync ----
    // warp grid: wm = wid&3 -> 32 rows, wn = wid>>2 -> 32 codes
    const int wm = wid & 3, wn = wid >> 2;
    const int l4 = lane >> 2, lm4 = lane & 3;
    const float* xh = sm + X_HI;
    const float* xl = sm + X_LO;
    const float* ehi = sm + E_HI;
    const float* elo = sm + E_LO;

    unsigned long long bkey[2][2] = {{~0ULL, ~0ULL}, {~0ULL, ~0ULL}};

#pragma unroll 1
    for (int ct = 0; ct < 4; ct++) {
        float dacc[2][4][4];
#pragma unroll
        for (int mt = 0; mt < 2; mt++)
#pragma unroll
            for (int nt = 0; nt < 4; nt++)
#pragma unroll
                for (int q = 0; q < 4; q++) dacc[mt][nt][q] = 0.f;

#pragma unroll 1
        for (int kc = 0; kc < 2; kc++) {
            __syncthreads();
            // load E chunk: [64 k][128 codes] hi+lo, conflict-free STS
            {
                const int k_lo = lane >> 3, c_lo = lane & 7;
#pragma unroll 1
                for (int g = wid; g < 256; g += 16) {
                    int k = (g & 15) * 4 + k_lo;
                    int code = (g >> 4) * 8 + c_lo;
                    size_t gi = (size_t)(ct * 128 + code) * HDIM + kc * 64 + k;
                    sm[E_HI + k * ESTRIDE + code] = g_ehi[gi];
                    sm[E_LO + k * ESTRIDE + code] = g_elo[gi];
                }
            }
            __syncthreads();

#pragma unroll 1
            for (int ks = 0; ks < 8; ks++) {
                const int kk = kc * 64 + ks * 8;
                float ahi[2][4], alo[2][4];
#pragma unroll
                for (int mt = 0; mt < 2; mt++) {
                    int r = wm * 32 + mt * 16 + l4;
                    ahi[mt][0] = xh[r * XSTRIDE + kk + lm4];
                    ahi[mt][1] = xh[(r + 8) * XSTRIDE + kk + lm4];
                    ahi[mt][2] = xh[r * XSTRIDE + kk + lm4 + 4];
                    ahi[mt][3] = xh[(r + 8) * XSTRIDE + kk + lm4 + 4];
                    alo[mt][0] = xl[r * XSTRIDE + kk + lm4];
                    alo[mt][1] = xl[(r + 8) * XSTRIDE + kk + lm4];
                    alo[mt][2] = xl[r * XSTRIDE + kk + lm4 + 4];
                    alo[mt][3] = xl[(r + 8) * XSTRIDE + kk + lm4 + 4];
                }
                float bhi[4][2], blo[4][2];
#pragma unroll
                for (int nt = 0; nt < 4; nt++) {
                    int col = wn * 32 + nt * 8 + l4;
                    int kb = ks * 8 + lm4;
                    bhi[nt][0] = ehi[kb * ESTRIDE + col];
                    bhi[nt][1] = ehi[(kb + 4) * ESTRIDE + col];
                    blo[nt][0] = elo[kb * ESTRIDE + col];
                    blo[nt][1] = elo[(kb + 4) * ESTRIDE + col];
                }
#pragma unroll
                for (int mt = 0; mt < 2; mt++)
#pragma unroll
                    for (int nt = 0; nt < 4; nt++) {
                        mma_tf32(dacc[mt][nt], ahi[mt], bhi[nt]);
                        mma_tf32(dacc[mt][nt], alo[mt], bhi[nt]);
                        mma_tf32(dacc[mt][nt], ahi[mt], blo[nt]);
                    }
            }
        }
        // tile epilogue: d = ||e||^2 - 2*dot; fold into per-row-slot best keys
#pragma unroll
        for (int nt = 0; nt < 4; nt++) {
            int code = ct * 128 + wn * 32 + nt * 8 + 2 * lm4;
            float en0 = sm[ENORM + code], en1 = sm[ENORM + code + 1];
#pragma unroll
            for (int mt = 0; mt < 2; mt++) {
                float d00 = fmaf(-2.f, dacc[mt][nt][0], en0);
                float d01 = fmaf(-2.f, dacc[mt][nt][1], en1);
                float d10 = fmaf(-2.f, dacc[mt][nt][2], en0);
                float d11 = fmaf(-2.f, dacc[mt][nt][3], en1);
                unsigned long long k00 = packkey(d00, code);
                unsigned long long k01 = packkey(d01, code + 1);
                unsigned long long k10 = packkey(d10, code);
                unsigned long long k11 = packkey(d11, code + 1);
                if (k00 < bkey[mt][0]) bkey[mt][0] = k00;
                if (k01 < bkey[mt][0]) bkey[mt][0] = k01;
                if (k10 < bkey[mt][1]) bkey[mt][1] = k10;
                if (k11 < bkey[mt][1]) bkey[mt][1] = k11;
            }
        }
    }

    // cross-lane / cross-warp argmin via packed smem atomicMin
#pragma unroll
    for (int mt = 0; mt < 2; mt++) {
        int r0 = wm * 32 + mt * 16 + l4;
        atomicMin(&s_best[r0], bkey[mt][0]);
        atomicMin(&s_best[r0 + 8], bkey[mt][1]);
    }
    __syncthreads();

    // ---- gather outputs ----
    if (tid < TM) {
        int bidx = (int)(s_best[tid] & 0xFFFFFFFFULL);
        size_t grow = (size_t)(row0 + tid);
        float4 p0 = *(const float4*)&g_probs[bidx * ADIM];
        float4 p1 = *(const float4*)&g_probs[bidx * ADIM + 4];
        *(float4*)&out[grow * ADIM]     = p0;
        *(float4*)&out[grow * ADIM + 4] = p1;
        out[(size_t)nrows * ADIM + grow] = g_value[bidx];
    }
}

// ---------------------------------------------------------------------------
extern "C" void kernel_launch(void* const* d_in, const int* in_sizes, int n_in,
                              void* d_out, int out_size) {
    const float* in = (const float*)d_in[0];
    const float* W1 = (const float*)d_in[1];
    const float* b1 = (const float*)d_in[2];
    const float* Wh = (const float*)d_in[3];
    const float* bh = (const float*)d_in[4];
    const float* E  = (const float*)d_in[5];
    const float* Wa = (const float*)d_in[6];
    const float* ba = (const float*)d_in[7];
    const float* Wv = (const float*)d_in[8];
    const float* bv = (const float*)d_in[9];
    float* out = (float*)d_out;

    const int nrows = in_sizes[0] / SDIM;  // 131072

    head_kernel<<<(KC + 255) / 256, 256>>>(E, Wa, ba, Wv, bv);

    const int smem_bytes = ARENA_FLOATS * (int)sizeof(float);  // 206,848 B
    cudaFuncSetAttribute(fused_kernel,
                         cudaFuncAttributeMaxDynamicSharedMemorySize, smem_bytes);
    fused_kernel<<<nrows / TM, NT, smem_bytes>>>(in, W1, b1, Wh, bh, out, nrows);
}

// round 6
// speedup vs baseline: 1.8906x; 1.8906x over previous
#include <cuda_runtime.h>
#include <cuda_bf16.h>
#include <math.h>
#include <stdint.h>

#define SDIM 64
#define HDIM 128
#define KC   512
#define ADIM 8
#define TM   128
#define NT   512
#define CAP  6144

// ---- shared arena (float/u32 offsets) ----
// MLP era:    s_in[128][68]@0 | s_w[128x128]@8704 | s_h[128][132]@25600
// screen era: x_f32[128][132]@0 | x_bf(u32)[128][68]@16896 |
//             e0(u32)[128][68]@25600 | e1@34304 | s_en@43008 | s_nx@43520 |
//             s_T@43648 | s_b32@43776 | s_fin(u64)@43904 | cand@44160 | cnt@50304
#define S_IN      0
#define SI_STRIDE 68
#define S_W       8704
#define S_H       25600
#define SH_STRIDE 132
#define X_F       0
#define XF_STRIDE 132
#define XBF_U32   16896
#define E0_U32    25600
#define E1_U32    34304
#define EB_STRIDE 68
#define S_EN      43008
#define S_NX      43520
#define S_T       43648
#define S_B32     43776
#define S_FIN     43904
#define CANDS     44160
#define CNT       50304
#define ARENA_FLOATS 50320   // 201,280 bytes

__device__ float g_probs[KC * ADIM];
__device__ float g_value[KC];
__device__ float g_enorm[KC];
__device__ uint32_t g_ebf[KC * HDIM / 2];   // bf16x2-packed codebook, [code][k/2]
__device__ int g_emax = 0;                  // max ||e||^2 as float bits (idempotent)

// ---------------- helpers ----------------
__device__ __forceinline__ float2 ffma2(float2 a, float2 b, float2 c) {
    float2 d;
    asm("fma.rn.f32x2 %0, %1, %2, %3;"
        : "=l"(reinterpret_cast<unsigned long long&>(d))
        : "l"(reinterpret_cast<unsigned long long&>(a)),
          "l"(reinterpret_cast<unsigned long long&>(b)),
          "l"(reinterpret_cast<unsigned long long&>(c)));
    return d;
}
// m16n8k16 bf16 mma, fp32 accumulate
__device__ __forceinline__ void mma_bf16(float c[4], const uint32_t a[4], const uint32_t b[2]) {
    asm volatile(
        "mma.sync.aligned.m16n8k16.row.col.f32.bf16.bf16.f32 "
        "{%0,%1,%2,%3}, {%4,%5,%6,%7}, {%8,%9}, {%0,%1,%2,%3};"
        : "+f"(c[0]), "+f"(c[1]), "+f"(c[2]), "+f"(c[3])
        : "r"(a[0]), "r"(a[1]), "r"(a[2]), "r"(a[3]), "r"(b[0]), "r"(b[1]));
}
__device__ __forceinline__ uint32_t fmap(float d) {
    uint32_t u = __float_as_uint(d);
    return (u >> 31) ? ~u : (u | 0x80000000u);
}
__device__ __forceinline__ float funmap(uint32_t m) {
    uint32_t u = (m & 0x80000000u) ? (m & 0x7FFFFFFFu) : ~m;
    return __uint_as_float(u);
}
__device__ __forceinline__ unsigned long long pk64(float d, int code) {
    return ((unsigned long long)fmap(d) << 32) | (uint32_t)code;
}

// ---------------------------------------------------------------------------
// Kernel 0: per-code heads + bf16 codebook + norms + global max norm.
// ---------------------------------------------------------------------------
__global__ void head_kernel(const float* __restrict__ E,
                            const float* __restrict__ Wa,
                            const float* __restrict__ ba,
                            const float* __restrict__ Wv,
                            const float* __restrict__ bv) {
    int c = blockIdx.x * blockDim.x + threadIdx.x;
    if (c >= KC) return;
    float logit[ADIM];
#pragma unroll
    for (int a = 0; a < ADIM; a++) logit[a] = ba[a];
    float en = 0.f, val = bv[0];
    float prev = 0.f;
    for (int k = 0; k < HDIM; k++) {
        float ev = E[c * HDIM + k];
        en  = fmaf(ev, ev, en);
        val = fmaf(ev, Wv[k], val);
        if (k & 1) {
            __nv_bfloat162 p = __floats2bfloat162_rn(prev, ev);  // x=even(low)
            g_ebf[c * 64 + (k >> 1)] = *reinterpret_cast<uint32_t*>(&p);
        } else prev = ev;
#pragma unroll
        for (int a = 0; a < ADIM; a++)
            logit[a] = fmaf(ev, Wa[k * ADIM + a], logit[a]);
    }
    float m = logit[0];
#pragma unroll
    for (int a = 1; a < ADIM; a++) m = fmaxf(m, logit[a]);
    float s = 0.f;
#pragma unroll
    for (int a = 0; a < ADIM; a++) { logit[a] = expf(logit[a] - m); s += logit[a]; }
    float inv = 1.f / s;
#pragma unroll
    for (int a = 0; a < ADIM; a++) g_probs[c * ADIM + a] = logit[a] * inv;
    g_value[c] = val;
    g_enorm[c] = en;
    atomicMax(&g_emax, __float_as_int(en));   // en >= 0: int order == float order
}

// ---------------------------------------------------------------------------
// Fused kernel: FFMA2 MLP -> bf16 mma screen (2 passes) -> exact fp32 rescore.
// ---------------------------------------------------------------------------
__global__ __launch_bounds__(NT, 1)
void fused_kernel(const float* __restrict__ in,
                  const float* __restrict__ W1,
                  const float* __restrict__ b1,
                  const float* __restrict__ Wh,
                  const float* __restrict__ bh,
                  const float* __restrict__ E,
                  float* __restrict__ out,
                  int nrows) {
    extern __shared__ float smf[];
    uint32_t* smu = reinterpret_cast<uint32_t*>(smf);
    unsigned long long* s_fin = reinterpret_cast<unsigned long long*>(smu + S_FIN);

    const int tid  = threadIdx.x;
    const int wid  = tid >> 5, lane = tid & 31;
    const int rbase = wid * 8;
    const int row0 = blockIdx.x * TM;

    float* s_in = smf + S_IN;
    float* s_w  = smf + S_W;
    float* s_h  = smf + S_H;

    // ---- load input tile + W1 ----
    for (int i = tid; i < TM * SDIM; i += NT) {
        int r = i >> 6, k = i & 63;
        s_in[r * SI_STRIDE + k] = in[(size_t)(row0 + r) * SDIM + k];
    }
    for (int i = tid; i < SDIM * HDIM; i += NT) s_w[i] = W1[i];
    __syncthreads();

    float2 acc[8][2];

    // ---- Phase 1: h = relu(in @ W1 + b1) ----
    {
        float4 bb = *(const float4*)&b1[4 * lane];
#pragma unroll
        for (int i = 0; i < 8; i++) {
            acc[i][0] = make_float2(bb.x, bb.y);
            acc[i][1] = make_float2(bb.z, bb.w);
        }
#pragma unroll 1
        for (int k4 = 0; k4 < SDIM; k4 += 4) {
            float a4[8][4];
#pragma unroll
            for (int i = 0; i < 8; i++)
                *(float4*)&a4[i][0] = *(const float4*)&s_in[(rbase + i) * SI_STRIDE + k4];
#pragma unroll
            for (int j = 0; j < 4; j++) {
                float4 b4 = *(const float4*)&s_w[(k4 + j) * HDIM + 4 * lane];
                float2 blo = make_float2(b4.x, b4.y), bhi = make_float2(b4.z, b4.w);
#pragma unroll
                for (int i = 0; i < 8; i++) {
                    float2 a2 = make_float2(a4[i][j], a4[i][j]);
                    acc[i][0] = ffma2(a2, blo, acc[i][0]);
                    acc[i][1] = ffma2(a2, bhi, acc[i][1]);
                }
            }
        }
    }
#pragma unroll
    for (int i = 0; i < 8; i++) {
        float4 v = make_float4(fmaxf(acc[i][0].x, 0.f), fmaxf(acc[i][0].y, 0.f),
                               fmaxf(acc[i][1].x, 0.f), fmaxf(acc[i][1].y, 0.f));
        *(float4*)&s_h[(rbase + i) * SH_STRIDE + 4 * lane] = v;
    }
    __syncthreads();
    for (int i = tid; i < HDIM * HDIM; i += NT) s_w[i] = Wh[i];
    __syncthreads();

    // ---- Phase 2: x = relu(h @ Wh + bh) ----
    {
        float4 bb = *(const float4*)&bh[4 * lane];
#pragma unroll
        for (int i = 0; i < 8; i++) {
            acc[i][0] = make_float2(bb.x, bb.y);
            acc[i][1] = make_float2(bb.z, bb.w);
        }
#pragma unroll 1
        for (int k4 = 0; k4 < HDIM; k4 += 4) {
            float a4[8][4];
#pragma unroll
            for (int i = 0; i < 8; i++)
                *(float4*)&a4[i][0] = *(const float4*)&s_h[(rbase + i) * SH_STRIDE + k4];
#pragma unroll
            for (int j = 0; j < 4; j++) {
                float4 b4 = *(const float4*)&s_w[(k4 + j) * HDIM + 4 * lane];
                float2 blo = make_float2(b4.x, b4.y), bhi = make_float2(b4.z, b4.w);
#pragma unroll
                for (int i = 0; i < 8; i++) {
                    float2 a2 = make_float2(a4[i][j], a4[i][j]);
                    acc[i][0] = ffma2(a2, blo, acc[i][0]);
                    acc[i][1] = ffma2(a2, bhi, acc[i][1]);
                }
            }
        }
    }
    __syncthreads();   // all MLP smem reads done; arena re-purposed

    // ---- epilogue: x -> fp32 tile + bf16 tile + row norms ----
    {
#pragma unroll
        for (int i = 0; i < 8; i++) {
            int r = rbase + i;
            float4 v = make_float4(fmaxf(acc[i][0].x, 0.f), fmaxf(acc[i][0].y, 0.f),
                                   fmaxf(acc[i][1].x, 0.f), fmaxf(acc[i][1].y, 0.f));
            *(float4*)&smf[X_F + r * XF_STRIDE + 4 * lane] = v;
            __nv_bfloat162 p0 = __floats2bfloat162_rn(v.x, v.y);
            __nv_bfloat162 p1 = __floats2bfloat162_rn(v.z, v.w);
            smu[XBF_U32 + r * EB_STRIDE + 2 * lane]     = *reinterpret_cast<uint32_t*>(&p0);
            smu[XBF_U32 + r * EB_STRIDE + 2 * lane + 1] = *reinterpret_cast<uint32_t*>(&p1);
            float nx = fmaf(v.x, v.x, fmaf(v.y, v.y, fmaf(v.z, v.z, v.w * v.w)));
#pragma unroll
            for (int off = 16; off; off >>= 1) nx += __shfl_xor_sync(0xffffffffu, nx, off);
            if (lane == 0) smf[S_NX + r] = nx;
        }
    }
    for (int i = tid; i < KC; i += NT) smf[S_EN + i] = g_enorm[i];
    if (tid < TM) smu[S_B32 + tid] = 0xFFFFFFFFu;

    // ---- screening: pass 0 = min, pass 1 = collect candidates ----
    const int wm = wid & 3, wn = wid >> 2;
    const int l4 = lane >> 2, lm4 = lane & 3;
    const uint32_t* xb = smu + XBF_U32;
    const uint4* esrc = reinterpret_cast<const uint4*>(g_ebf);

    uint32_t mk[2][2] = {{0xFFFFFFFFu, 0xFFFFFFFFu}, {0xFFFFFFFFu, 0xFFFFFFFFu}};
    float tc[2][2];

#pragma unroll 1
    for (int pass = 0; pass < 2; pass++) {
        if (pass == 1) {
#pragma unroll
            for (int mt = 0; mt < 2; mt++) {
                tc[mt][0] = smf[S_T + wm * 32 + mt * 16 + l4];
                tc[mt][1] = smf[S_T + wm * 32 + mt * 16 + l4 + 8];
            }
        }
        // preload E chunk 0 into e0
        {
            uint32_t* eb = smu + E0_U32;
#pragma unroll
            for (int s = 0; s < 4; s++) {
                int i = tid + s * NT;
                int code = i >> 4, q = i & 15;
                uint4 v = esrc[code * 16 + q];
                *(uint4*)&eb[code * EB_STRIDE + q * 4] = v;
            }
        }
        __syncthreads();

#pragma unroll 1
        for (int ct = 0; ct < 4; ct++) {
            const uint32_t* eb = smu + ((ct & 1) ? E1_U32 : E0_U32);
            uint4 pf[4];
            if (ct < 3) {
#pragma unroll
                for (int s = 0; s < 4; s++) {
                    int i = tid + s * NT;
                    int code = i >> 4, q = i & 15;
                    pf[s] = esrc[((ct + 1) * 128 + code) * 16 + q];
                }
            }

            float dacc[2][4][4];
#pragma unroll
            for (int mt = 0; mt < 2; mt++)
#pragma unroll
                for (int nt = 0; nt < 4; nt++)
#pragma unroll
                    for (int q = 0; q < 4; q++) dacc[mt][nt][q] = 0.f;

#pragma unroll
            for (int ks = 0; ks < 8; ks++) {
                const int ko = 8 * ks + lm4;
                uint32_t a[2][4], b[4][2];
#pragma unroll
                for (int mt = 0; mt < 2; mt++) {
                    int r = wm * 32 + mt * 16 + l4;
                    a[mt][0] = xb[r * EB_STRIDE + ko];
                    a[mt][1] = xb[(r + 8) * EB_STRIDE + ko];
                    a[mt][2] = xb[r * EB_STRIDE + ko + 4];
                    a[mt][3] = xb[(r + 8) * EB_STRIDE + ko + 4];
                }
#pragma unroll
                for (int nt = 0; nt < 4; nt++) {
                    int cc = wn * 32 + nt * 8 + l4;
                    b[nt][0] = eb[cc * EB_STRIDE + ko];
                    b[nt][1] = eb[cc * EB_STRIDE + ko + 4];
                }
#pragma unroll
                for (int mt = 0; mt < 2; mt++)
#pragma unroll
                    for (int nt = 0; nt < 4; nt++)
                        mma_bf16(dacc[mt][nt], a[mt], b[nt]);
            }

            // epilogue of this code tile
#pragma unroll
            for (int nt = 0; nt < 4; nt++) {
                int code = ct * 128 + wn * 32 + nt * 8 + 2 * lm4;
                float en0 = smf[S_EN + code], en1 = smf[S_EN + code + 1];
#pragma unroll
                for (int mt = 0; mt < 2; mt++) {
                    float d00 = fmaf(-2.f, dacc[mt][nt][0], en0);
                    float d01 = fmaf(-2.f, dacc[mt][nt][1], en1);
                    float d10 = fmaf(-2.f, dacc[mt][nt][2], en0);
                    float d11 = fmaf(-2.f, dacc[mt][nt][3], en1);
                    if (pass == 0) {
                        uint32_t m0 = fmap(d00), m1 = fmap(d01);
                        uint32_t m2 = fmap(d10), m3 = fmap(d11);
                        mk[mt][0] = min(mk[mt][0], min(m0, m1));
                        mk[mt][1] = min(mk[mt][1], min(m2, m3));
                    } else {
                        int row = wm * 32 + mt * 16 + l4;
                        if (d00 <= tc[mt][0]) {
                            int p = atomicAdd((int*)&smu[CNT], 1);
                            if (p < CAP) smu[CANDS + p] = ((uint32_t)row << 16) | code;
                        }
                        if (d01 <= tc[mt][0]) {
                            int p = atomicAdd((int*)&smu[CNT], 1);
                            if (p < CAP) smu[CANDS + p] = ((uint32_t)row << 16) | (code + 1);
                        }
                        if (d10 <= tc[mt][1]) {
                            int p = atomicAdd((int*)&smu[CNT], 1);
                            if (p < CAP) smu[CANDS + p] = ((uint32_t)(row + 8) << 16) | code;
                        }
                        if (d11 <= tc[mt][1]) {
                            int p = atomicAdd((int*)&smu[CNT], 1);
                            if (p < CAP) smu[CANDS + p] = ((uint32_t)(row + 8) << 16) | (code + 1);
                        }
                    }
                }
            }

            if (ct < 3) {
                uint32_t* ebn = smu + (((ct + 1) & 1) ? E1_U32 : E0_U32);
#pragma unroll
                for (int s = 0; s < 4; s++) {
                    int i = tid + s * NT;
                    int code = i >> 4, q = i & 15;
                    *(uint4*)&ebn[code * EB_STRIDE + q * 4] = pf[s];
                }
            }
            __syncthreads();
        }

        if (pass == 0) {
            // fold per-thread mins into per-row screen min
#pragma unroll
            for (int mt = 0; mt < 2; mt++) {
                int row = wm * 32 + mt * 16 + l4;
                atomicMin(&smu[S_B32 + row], mk[mt][0]);
                atomicMin(&smu[S_B32 + row + 8], mk[mt][1]);
            }
            __syncthreads();
            if (tid < TM) {
                float dmin = funmap(smu[S_B32 + tid]);
                float nx = sqrtf(smf[S_NX + tid]);
                float em = sqrtf(__int_as_float(g_emax));
                // rigorous bf16-screen error bound ~2^-6*nx*em; 0.045 > 1.4x safety
                smf[S_T + tid] = dmin + 0.045f * nx * em + 1e-6f;
                s_fin[tid] = ~0ULL;
            }
            if (tid == 0) smu[CNT] = 0;
            __syncthreads();
        }
    }

    // ---- exact fp32 rescore of candidates ----
    int cnt = (int)smu[CNT];
    if (cnt > CAP) cnt = CAP;
#pragma unroll 1
    for (int idx = wid; idx < cnt; idx += 16) {
        uint32_t ent = smu[CANDS + idx];
        int row = ent >> 16, code = ent & 0xFFFF;
        float4 xv = *(const float4*)&smf[X_F + row * XF_STRIDE + 4 * lane];
        float4 ev = *(const float4*)&E[(size_t)code * HDIM + 4 * lane];
        float p = fmaf(xv.x, ev.x, fmaf(xv.y, ev.y, fmaf(xv.z, ev.z, xv.w * ev.w)));
#pragma unroll
        for (int off = 16; off; off >>= 1) p += __shfl_xor_sync(0xffffffffu, p, off);
        if (lane == 0) {
            float d = fmaf(-2.f, p, smf[S_EN + code]);
            atomicMin(&s_fin[row], pk64(d, code));
        }
    }
    __syncthreads();

    // ---- gather outputs ----
    if (tid < TM) {
        int bidx = (int)(s_fin[tid] & 0xFFFFFFFFULL);
        size_t grow = (size_t)(row0 + tid);
        float4 p0 = *(const float4*)&g_probs[bidx * ADIM];
        float4 p1 = *(const float4*)&g_probs[bidx * ADIM + 4];
        *(float4*)&out[grow * ADIM]     = p0;
        *(float4*)&out[grow * ADIM + 4] = p1;
        out[(size_t)nrows * ADIM + grow] = g_value[bidx];
    }
}

// ---------------------------------------------------------------------------
extern "C" void kernel_launch(void* const* d_in, const int* in_sizes, int n_in,
                              void* d_out, int out_size) {
    const float* in = (const float*)d_in[0];
    const float* W1 = (const float*)d_in[1];
    const float* b1 = (const float*)d_in[2];
    const float* Wh = (const float*)d_in[3];
    const float* bh = (const float*)d_in[4];
    const float* E  = (const float*)d_in[5];
    const float* Wa = (const float*)d_in[6];
    const float* ba = (const float*)d_in[7];
    const float* Wv = (const float*)d_in[8];
    const float* bv = (const float*)d_in[9];
    float* out = (float*)d_out;

    const int nrows = in_sizes[0] / SDIM;  // 131072

    head_kernel<<<(KC + 255) / 256, 256>>>(E, Wa, ba, Wv, bv);

    const int smem_bytes = ARENA_FLOATS * (int)sizeof(float);  // 201,280 B
    cudaFuncSetAttribute(fused_kernel,
                         cudaFuncAttributeMaxDynamicSharedMemorySize, smem_bytes);
    fused_kernel<<<nrows / TM, NT, smem_bytes>>>(in, W1, b1, Wh, bh, E, out, nrows);
}

// round 7
// speedup vs baseline: 2.0763x; 1.0983x over previous
#include <cuda_runtime.h>
#include <cuda_bf16.h>
#include <math.h>
#include <stdint.h>

#define SDIM 64
#define HDIM 128
#define KC   512
#define ADIM 8
#define TM   64
#define NT   256

// ---- smem arena (u32 offsets) ----
// MLP era:    s_in[64][68]@0 | s_w[64][128]@4352 | s_h[64][132]@12544 (end 20992)
// screen era: x_bf[64][68]@0 | e_b[64][68]@4352 | dist[64][260]@8704 (end 25344)
// common:     s_en@25344 | s_nx2@25856 | s_T@25920 | s_minu@25984 | s_cnt@26048 |
//             s_cand(u16[64][16])@26112 | s_fin@26624 | end 26688
#define S_IN    0
#define SI_STR  68
#define S_W     4352
#define S_H     12544
#define SH_STR  132
#define X_BF    0
#define E_B     4352
#define EB_STR  68
#define DIST    8704
#define D_STR   260
#define S_EN    25344
#define S_NX2   25856
#define S_T     25920
#define S_MINU  25984
#define S_CNT   26048
#define S_CAND  26112
#define S_FIN   26624
#define ARENA_U32 26688   // 106,752 bytes -> 2 CTAs/SM

__device__ float g_probs[KC * ADIM];
__device__ float g_value[KC];
__device__ float g_enorm[KC];
__device__ uint32_t g_ebf[KC * HDIM / 2];   // bf16x2 codebook [code][k/2], even k low
__device__ int g_emax = 0;

// ---------------- helpers ----------------
__device__ __forceinline__ float2 ffma2(float2 a, float2 b, float2 c) {
    float2 d;
    asm("fma.rn.f32x2 %0, %1, %2, %3;"
        : "=l"(reinterpret_cast<unsigned long long&>(d))
        : "l"(reinterpret_cast<unsigned long long&>(a)),
          "l"(reinterpret_cast<unsigned long long&>(b)),
          "l"(reinterpret_cast<unsigned long long&>(c)));
    return d;
}
__device__ __forceinline__ void mma_bf16(float c[4], const uint32_t a[4], const uint32_t b[2]) {
    asm volatile(
        "mma.sync.aligned.m16n8k16.row.col.f32.bf16.bf16.f32 "
        "{%0,%1,%2,%3}, {%4,%5,%6,%7}, {%8,%9}, {%0,%1,%2,%3};"
        : "+f"(c[0]), "+f"(c[1]), "+f"(c[2]), "+f"(c[3])
        : "r"(a[0]), "r"(a[1]), "r"(a[2]), "r"(a[3]), "r"(b[0]), "r"(b[1]));
}
__device__ __forceinline__ uint32_t fmap(float d) {
    uint32_t u = __float_as_uint(d);
    return (u >> 31) ? ~u : (u | 0x80000000u);
}
__device__ __forceinline__ float funmap(uint32_t m) {
    uint32_t u = (m & 0x80000000u) ? (m & 0x7FFFFFFFu) : ~m;
    return __uint_as_float(u);
}
__device__ __forceinline__ unsigned long long pk64(float d, int code) {
    return ((unsigned long long)fmap(d) << 32) | (uint32_t)code;
}

// ---------------------------------------------------------------------------
// Kernel 0: per-code heads + bf16 codebook + norms + global max norm.
// ---------------------------------------------------------------------------
__global__ void head_kernel(const float* __restrict__ E,
                            const float* __restrict__ Wa,
                            const float* __restrict__ ba,
                            const float* __restrict__ Wv,
                            const float* __restrict__ bv) {
    int c = blockIdx.x * blockDim.x + threadIdx.x;
    if (c >= KC) return;
    float logit[ADIM];
#pragma unroll
    for (int a = 0; a < ADIM; a++) logit[a] = ba[a];
    float en = 0.f, val = bv[0], prev = 0.f;
    for (int k = 0; k < HDIM; k++) {
        float ev = E[c * HDIM + k];
        en  = fmaf(ev, ev, en);
        val = fmaf(ev, Wv[k], val);
        if (k & 1) {
            __nv_bfloat162 p = __floats2bfloat162_rn(prev, ev);
            g_ebf[c * 64 + (k >> 1)] = *reinterpret_cast<uint32_t*>(&p);
        } else prev = ev;
#pragma unroll
        for (int a = 0; a < ADIM; a++)
            logit[a] = fmaf(ev, Wa[k * ADIM + a], logit[a]);
    }
    float m = logit[0];
#pragma unroll
    for (int a = 1; a < ADIM; a++) m = fmaxf(m, logit[a]);
    float s = 0.f;
#pragma unroll
    for (int a = 0; a < ADIM; a++) { logit[a] = expf(logit[a] - m); s += logit[a]; }
    float inv = 1.f / s;
#pragma unroll
    for (int a = 0; a < ADIM; a++) g_probs[c * ADIM + a] = logit[a] * inv;
    g_value[c] = val;
    g_enorm[c] = en;
    atomicMax(&g_emax, __float_as_int(en));
}

// ---------------------------------------------------------------------------
// Fused kernel: 64 rows/CTA, 256 threads, 2 CTAs/SM.
// FFMA2 MLP (x stays in registers) -> bf16 mma screen with smem-stored
// distances -> threshold scan -> exact fp32 rescore by owning warp.
// ---------------------------------------------------------------------------
__global__ __launch_bounds__(NT, 2)
void fused_kernel(const float* __restrict__ in,
                  const float* __restrict__ W1,
                  const float* __restrict__ b1,
                  const float* __restrict__ Wh,
                  const float* __restrict__ bh,
                  const float* __restrict__ E,
                  float* __restrict__ out,
                  int nrows) {
    extern __shared__ float smf[];
    uint32_t* smu = reinterpret_cast<uint32_t*>(smf);
    unsigned short* s_cand = reinterpret_cast<unsigned short*>(smu + S_CAND);

    const int tid  = threadIdx.x;
    const int wid  = tid >> 5, lane = tid & 31;
    const int rbase = wid * 8;                  // 8 warps x 8 rows
    const int row0 = blockIdx.x * TM;

    float* s_in = smf + S_IN;
    float* s_w  = smf + S_W;
    float* s_h  = smf + S_H;

    // ---- load input tile + W1 ----
    for (int i = tid; i < TM * SDIM; i += NT) {
        int r = i >> 6, k = i & 63;
        s_in[r * SI_STR + k] = in[(size_t)(row0 + r) * SDIM + k];
    }
    for (int i = tid; i < SDIM * HDIM; i += NT) s_w[i] = W1[i];
    __syncthreads();

    float2 acc[8][2];

    // ---- Phase 1: h = relu(in @ W1 + b1) ----
    {
        float4 bb = *(const float4*)&b1[4 * lane];
#pragma unroll
        for (int i = 0; i < 8; i++) {
            acc[i][0] = make_float2(bb.x, bb.y);
            acc[i][1] = make_float2(bb.z, bb.w);
        }
#pragma unroll 1
        for (int k4 = 0; k4 < SDIM; k4 += 4) {
            float a4[8][4];
#pragma unroll
            for (int i = 0; i < 8; i++)
                *(float4*)&a4[i][0] = *(const float4*)&s_in[(rbase + i) * SI_STR + k4];
#pragma unroll
            for (int j = 0; j < 4; j++) {
                float4 b4 = *(const float4*)&s_w[(k4 + j) * HDIM + 4 * lane];
                float2 blo = make_float2(b4.x, b4.y), bhi = make_float2(b4.z, b4.w);
#pragma unroll
                for (int i = 0; i < 8; i++) {
                    float2 a2 = make_float2(a4[i][j], a4[i][j]);
                    acc[i][0] = ffma2(a2, blo, acc[i][0]);
                    acc[i][1] = ffma2(a2, bhi, acc[i][1]);
                }
            }
        }
    }
#pragma unroll
    for (int i = 0; i < 8; i++) {
        float4 v = make_float4(fmaxf(acc[i][0].x, 0.f), fmaxf(acc[i][0].y, 0.f),
                               fmaxf(acc[i][1].x, 0.f), fmaxf(acc[i][1].y, 0.f));
        *(float4*)&s_h[(rbase + i) * SH_STR + 4 * lane] = v;
    }

    // ---- Phase 2: x = relu(h @ Wh + bh), Wh streamed in two 64-k chunks ----
    {
        float4 bb = *(const float4*)&bh[4 * lane];
#pragma unroll
        for (int i = 0; i < 8; i++) {
            acc[i][0] = make_float2(bb.x, bb.y);
            acc[i][1] = make_float2(bb.z, bb.w);
        }
#pragma unroll 1
        for (int kc = 0; kc < 2; kc++) {
            __syncthreads();   // prior s_w readers done (and P1 s_h writes visible)
            for (int i = tid; i < 64 * HDIM; i += NT)
                s_w[i] = Wh[kc * 64 * HDIM + i];
            __syncthreads();
#pragma unroll 1
            for (int k4 = 0; k4 < 64; k4 += 4) {
                float a4[8][4];
#pragma unroll
                for (int i = 0; i < 8; i++)
                    *(float4*)&a4[i][0] =
                        *(const float4*)&s_h[(rbase + i) * SH_STR + kc * 64 + k4];
#pragma unroll
                for (int j = 0; j < 4; j++) {
                    float4 b4 = *(const float4*)&s_w[(k4 + j) * HDIM + 4 * lane];
                    float2 blo = make_float2(b4.x, b4.y), bhi = make_float2(b4.z, b4.w);
#pragma unroll
                    for (int i = 0; i < 8; i++) {
                        float2 a2 = make_float2(a4[i][j], a4[i][j]);
                        acc[i][0] = ffma2(a2, blo, acc[i][0]);
                        acc[i][1] = ffma2(a2, bhi, acc[i][1]);
                    }
                }
            }
        }
    }

    // ---- finalize x in registers; emit bf16 tile + row norms ----
    float4 xr[8];
#pragma unroll
    for (int i = 0; i < 8; i++) {
        xr[i] = make_float4(fmaxf(acc[i][0].x, 0.f), fmaxf(acc[i][0].y, 0.f),
                            fmaxf(acc[i][1].x, 0.f), fmaxf(acc[i][1].y, 0.f));
        __nv_bfloat162 p0 = __floats2bfloat162_rn(xr[i].x, xr[i].y);
        __nv_bfloat162 p1 = __floats2bfloat162_rn(xr[i].z, xr[i].w);
        // x_bf region overlays s_in (dead since phase 1) — safe pre-sync
        smu[X_BF + (rbase + i) * EB_STR + 2 * lane]     = *reinterpret_cast<uint32_t*>(&p0);
        smu[X_BF + (rbase + i) * EB_STR + 2 * lane + 1] = *reinterpret_cast<uint32_t*>(&p1);
        float nx = fmaf(xr[i].x, xr[i].x, fmaf(xr[i].y, xr[i].y,
                   fmaf(xr[i].z, xr[i].z, xr[i].w * xr[i].w)));
#pragma unroll
        for (int off = 16; off; off >>= 1) nx += __shfl_xor_sync(0xffffffffu, nx, off);
        if (lane == 0) smf[S_NX2 + rbase + i] = nx;   // region beyond MLP arena
    }
    for (int i = tid; i < KC; i += NT) smf[S_EN + i] = g_enorm[i];
    if (tid < TM) { smu[S_MINU + tid] = 0xFFFFFFFFu; smu[S_CNT + tid] = 0; }

    // ---- screen: 8 chunks of 64 codes, bf16 mma, distances stored in smem ----
    const int wm = wid & 1, wn = wid >> 1;       // 2 x 4 warp grid
    const int l4 = lane >> 2, lm4 = lane & 3;
    const uint32_t* xb = smu + X_BF;
    uint32_t* eb = smu + E_B;
    const uint4* esrc = reinterpret_cast<const uint4*>(g_ebf);

    uint32_t mk[2][2] = {{0xFFFFFFFFu, 0xFFFFFFFFu}, {0xFFFFFFFFu, 0xFFFFFFFFu}};

    uint4 pf[4];
#pragma unroll
    for (int s = 0; s < 4; s++) {
        int i = tid + s * NT;
        pf[s] = esrc[(i >> 4) * 16 + (i & 15)];
    }
    __syncthreads();   // MLP arena released; inits visible

#pragma unroll 1
    for (int ch = 0; ch < 8; ch++) {
#pragma unroll
        for (int s = 0; s < 4; s++) {
            int i = tid + s * NT;
            *(uint4*)&eb[(i >> 4) * EB_STR + (i & 15) * 4] = pf[s];
        }
        __syncthreads();
        if (ch < 7) {
#pragma unroll
            for (int s = 0; s < 4; s++) {
                int i = tid + s * NT;
                pf[s] = esrc[((ch + 1) * 64 + (i >> 4)) * 16 + (i & 15)];
            }
        }

        float dacc[2][2][4];
#pragma unroll
        for (int mt = 0; mt < 2; mt++)
#pragma unroll
            for (int nt = 0; nt < 2; nt++)
#pragma unroll
                for (int q = 0; q < 4; q++) dacc[mt][nt][q] = 0.f;

#pragma unroll
        for (int ks = 0; ks < 8; ks++) {
            const int ko = 8 * ks + lm4;
            uint32_t a[2][4], b[2][2];
#pragma unroll
            for (int mt = 0; mt < 2; mt++) {
                int r = wm * 32 + mt * 16 + l4;
                a[mt][0] = xb[r * EB_STR + ko];
                a[mt][1] = xb[(r + 8) * EB_STR + ko];
                a[mt][2] = xb[r * EB_STR + ko + 4];
                a[mt][3] = xb[(r + 8) * EB_STR + ko + 4];
            }
#pragma unroll
            for (int nt = 0; nt < 2; nt++) {
                int cc = wn * 16 + nt * 8 + l4;
                b[nt][0] = eb[cc * EB_STR + ko];
                b[nt][1] = eb[cc * EB_STR + ko + 4];
            }
#pragma unroll
            for (int mt = 0; mt < 2; mt++)
#pragma unroll
                for (int nt = 0; nt < 2; nt++)
                    mma_bf16(dacc[mt][nt], a[mt], b[nt]);
        }

        // epilogue: d = en - 2*dot, round to bf16 (stored + min-tracked same)
#pragma unroll
        for (int nt = 0; nt < 2; nt++) {
            int code0 = ch * 64 + wn * 16 + nt * 8 + 2 * lm4;
            float en0 = smf[S_EN + code0], en1 = smf[S_EN + code0 + 1];
#pragma unroll
            for (int mt = 0; mt < 2; mt++) {
                int r = wm * 32 + mt * 16 + l4;
                float d00 = fmaf(-2.f, dacc[mt][nt][0], en0);
                float d01 = fmaf(-2.f, dacc[mt][nt][1], en1);
                float d10 = fmaf(-2.f, dacc[mt][nt][2], en0);
                float d11 = fmaf(-2.f, dacc[mt][nt][3], en1);
                __nv_bfloat162 p0 = __floats2bfloat162_rn(d00, d01);
                __nv_bfloat162 p1 = __floats2bfloat162_rn(d10, d11);
                uint32_t u0 = *reinterpret_cast<uint32_t*>(&p0);
                uint32_t u1 = *reinterpret_cast<uint32_t*>(&p1);
                smu[DIST + r * D_STR + (code0 >> 1)]       = u0;
                smu[DIST + (r + 8) * D_STR + (code0 >> 1)] = u1;
                float2 f0 = __bfloat1622float2(p0);
                float2 f1 = __bfloat1622float2(p1);
                mk[mt][0] = min(mk[mt][0], min(fmap(f0.x), fmap(f0.y)));
                mk[mt][1] = min(mk[mt][1], min(fmap(f1.x), fmap(f1.y)));
            }
        }
        __syncthreads();   // eb consumed before next chunk overwrite
    }

    // per-row screen min
#pragma unroll
    for (int mt = 0; mt < 2; mt++) {
        int r = wm * 32 + mt * 16 + l4;
        atomicMin(&smu[S_MINU + r], mk[mt][0]);
        atomicMin(&smu[S_MINU + r + 8], mk[mt][1]);
    }
    __syncthreads();

    // thresholds
    if (tid < TM) {
        float dmin = funmap(smu[S_MINU + tid]);
        float nx2 = smf[S_NX2 + tid];
        float em = sqrtf(__int_as_float(g_emax));
        smf[S_T + tid] = dmin + 0.045f * sqrtf(nx2) * em
                       + 0.00390625f * (nx2 + 1.f) + 1e-6f;
    }
    __syncthreads();

    // ---- scan stored distances, collect candidates ----
    {
        int row = tid >> 2, q = tid & 3;
        float T = smf[S_T + row];
        const uint32_t* dr = smu + DIST + row * D_STR + q * 64;
#pragma unroll 1
        for (int j = 0; j < 16; j++) {
            uint4 v = *(const uint4*)&dr[j * 4];
            uint32_t ws[4] = {v.x, v.y, v.z, v.w};
#pragma unroll
            for (int w = 0; w < 4; w++) {
                __nv_bfloat162 p = *reinterpret_cast<__nv_bfloat162*>(&ws[w]);
                float2 f = __bfloat1622float2(p);
                int code = (q * 64 + j * 4 + w) * 2;
                if (f.x <= T) {
                    int pos = atomicAdd((int*)&smu[S_CNT + row], 1);
                    if (pos < 16) s_cand[row * 16 + pos] = (unsigned short)code;
                }
                if (f.y <= T) {
                    int pos = atomicAdd((int*)&smu[S_CNT + row], 1);
                    if (pos < 16) s_cand[row * 16 + pos] = (unsigned short)(code + 1);
                }
            }
        }
    }
    __syncthreads();

    // ---- exact fp32 rescore by owning warp (x in registers) ----
#pragma unroll 1
    for (int i = 0; i < 8; i++) {
        int row = rbase + i;
        int cnt = (int)smu[S_CNT + row];
        unsigned long long best = ~0ULL;
        if (cnt <= 16) {
#pragma unroll 1
            for (int j = 0; j < cnt; j++) {
                int code = s_cand[row * 16 + j];
                float4 ev = *(const float4*)&E[(size_t)code * HDIM + 4 * lane];
                float p = fmaf(xr[i].x, ev.x, fmaf(xr[i].y, ev.y,
                          fmaf(xr[i].z, ev.z, xr[i].w * ev.w)));
#pragma unroll
                for (int off = 16; off; off >>= 1)
                    p += __shfl_xor_sync(0xffffffffu, p, off);
                unsigned long long k = pk64(fmaf(-2.f, p, smf[S_EN + code]), code);
                if (k < best) best = k;
            }
        } else {
            // provable fallback: rescore all codes (cold path)
#pragma unroll 1
            for (int code = 0; code < KC; code++) {
                float4 ev = *(const float4*)&E[(size_t)code * HDIM + 4 * lane];
                float p = fmaf(xr[i].x, ev.x, fmaf(xr[i].y, ev.y,
                          fmaf(xr[i].z, ev.z, xr[i].w * ev.w)));
#pragma unroll
                for (int off = 16; off; off >>= 1)
                    p += __shfl_xor_sync(0xffffffffu, p, off);
                unsigned long long k = pk64(fmaf(-2.f, p, smf[S_EN + code]), code);
                if (k < best) best = k;
            }
        }
        if (lane == 0) smu[S_FIN + row] = (uint32_t)(best & 0xFFFFFFFFULL);
    }
    __syncthreads();

    // ---- gather outputs ----
    if (tid < TM) {
        int bidx = (int)smu[S_FIN + tid];
        size_t grow = (size_t)(row0 + tid);
        float4 p0 = *(const float4*)&g_probs[bidx * ADIM];
        float4 p1 = *(const float4*)&g_probs[bidx * ADIM + 4];
        *(float4*)&out[grow * ADIM]     = p0;
        *(float4*)&out[grow * ADIM + 4] = p1;
        out[(size_t)nrows * ADIM + grow] = g_value[bidx];
    }
}

// ---------------------------------------------------------------------------
extern "C" void kernel_launch(void* const* d_in, const int* in_sizes, int n_in,
                              void* d_out, int out_size) {
    const float* in = (const float*)d_in[0];
    const float* W1 = (const float*)d_in[1];
    const float* b1 = (const float*)d_in[2];
    const float* Wh = (const float*)d_in[3];
    const float* bh = (const float*)d_in[4];
    const float* E  = (const float*)d_in[5];
    const float* Wa = (const float*)d_in[6];
    const float* ba = (const float*)d_in[7];
    const float* Wv = (const float*)d_in[8];
    const float* bv = (const float*)d_in[9];
    float* out = (float*)d_out;

    const int nrows = in_sizes[0] / SDIM;  // 131072

    head_kernel<<<(KC + 255) / 256, 256>>>(E, Wa, ba, Wv, bv);

    const int smem_bytes = ARENA_U32 * (int)sizeof(uint32_t);  // 106,752 B
    cudaFuncSetAttribute(fused_kernel,
                         cudaFuncAttributeMaxDynamicSharedMemorySize, smem_bytes);
    fused_kernel<<<nrows / TM, NT, smem_bytes>>>(in, W1, b1, Wh, bh, E, out, nrows);
}